// round 1
// baseline (speedup 1.0000x reference)
#include <cuda_runtime.h>
#include <math.h>

#define Nn   16
#define Cc   256
#define C1c  128
#define C4c  64
#define Hh   56
#define Wc   56
#define HWc  3136
#define Pc   (Nn*HWc)
#define EPSf 1e-5f

// ---------------- scratch (device globals; no allocations) ----------------
__device__ float g_y  [Nn*Cc *HWc];   // gelu(bn(mlp)) ; ch 0..127 include +pos_h
__device__ float g_cat[Nn*C1c*HWc];   // [xh(64), xw(64)]
__device__ float g_t1 [Nn*C1c*HWc];   // after fuse_h + gelu(bn) + pos_w
__device__ float g_u1 [Nn*C1c*HWc];   // after fuse_w
__device__ float g_x2h[Nn*C1c*HWc];
__device__ float g_x2w[Nn*C1c*HWc];
__device__ float g_x2n[Nn*C1c*HWc];   // recombined x2
__device__ float g_att[Nn*C1c];
__device__ float g_a  [Nn*C1c*3];

__device__ __forceinline__ float gelu_f(float x) {
    return 0.5f * x * (1.0f + erff(x * 0.7071067811865476f));
}

// packed f32x2 helpers (FFMA2 path: 2x fp32 throughput on sm_103a)
__device__ __forceinline__ unsigned long long pk2(float lo, float hi) {
    unsigned long long r;
    asm("mov.b64 %0, {%1, %2};" : "=l"(r) : "f"(lo), "f"(hi));
    return r;
}
__device__ __forceinline__ void fma2(unsigned long long& d, unsigned long long a, unsigned long long b) {
    asm("fma.rn.f32x2 %0, %1, %2, %0;" : "+l"(d) : "l"(a), "l"(b));
}
__device__ __forceinline__ float2 upk2(unsigned long long v) {
    float2 r;
    asm("mov.b64 {%0, %1}, %2;" : "=f"(r.x), "=f"(r.y) : "l"(v));
    return r;
}

// ---------------------------------------------------------------------------
// Generic pointwise GEMM over pixels: out[o,q] = sum_c W[o*Cin+c] * in[c,q]
// in = channel-concat of (inA: cinA channels) then (inB: Cin-cinA channels),
// each stored NCHW with given per-image stride.
// Block tile 128 outputs x 128 pixels, 256 threads, 8x8 micro-tile, K-chunk 16,
// double-buffered smem, packed f32x2 accumulation.
// EPI: 0 none; 1 (+bias,BN,gelu,+pos if o<128); 2 (BN,gelu,+pos)
// ---------------------------------------------------------------------------
template<int EPI>
__global__ __launch_bounds__(256, 2)
void gemm_k(const float* __restrict__ Wm, int Cin,
            const float* __restrict__ inA, int cinA, int strA,
            const float* __restrict__ inB, int strB,
            float* __restrict__ out, int strO,
            const float* __restrict__ e_bias,
            const float* __restrict__ e_g, const float* __restrict__ e_b,
            const float* __restrict__ e_m, const float* __restrict__ e_v,
            const float* __restrict__ e_pos)
{
    __shared__ float Ws[2][16][132];
    __shared__ float Bs[2][16][132];

    const int tid = threadIdx.x;
    const int tx = tid & 15, ty = tid >> 4;
    const int q0 = blockIdx.x * 128;
    const int o0 = blockIdx.y * 128;

    // B-tile slot geometry (2 float4 slots per thread, fixed pixel position)
    int skk0, skk1, sn0, sn1, shw0, shw1, sp40, sp41;
    {
        int s = tid;          skk0 = s >> 5; sp40 = (s & 31) << 2;
        int q = q0 + sp40;    sn0 = q / HWc; shw0 = q - sn0 * HWc;
        s = tid + 256;        skk1 = s >> 5; sp41 = (s & 31) << 2;
        q = q0 + sp41;        sn1 = q / HWc; shw1 = q - sn1 * HWc;
    }
    // A-tile slot geometry
    const int aoo0 = tid >> 2,         akk0 = (tid & 3) << 2;
    const int aoo1 = (tid + 256) >> 2, akk1 = (tid & 3) << 2;

    unsigned long long acc[8][4];
#pragma unroll
    for (int i = 0; i < 8; i++)
#pragma unroll
        for (int j = 0; j < 4; j++) acc[i][j] = 0ull;

    const int nk = Cin >> 4;
    float4 ra0, ra1, rb0, rb1;

#define GEMM_FETCH(K0)                                                                   \
    do {                                                                                 \
        ra0 = *reinterpret_cast<const float4*>(&Wm[(long)(o0 + aoo0) * Cin + (K0) + akk0]); \
        ra1 = *reinterpret_cast<const float4*>(&Wm[(long)(o0 + aoo1) * Cin + (K0) + akk1]); \
        {                                                                                \
            int c = (K0) + skk0;                                                         \
            const float* p = (c < cinA)                                                  \
                ? inA + (long)sn0 * strA + (long)c * HWc + shw0                          \
                : inB + (long)sn0 * strB + (long)(c - cinA) * HWc + shw0;                \
            rb0 = *reinterpret_cast<const float4*>(p);                                   \
        }                                                                                \
        {                                                                                \
            int c = (K0) + skk1;                                                         \
            const float* p = (c < cinA)                                                  \
                ? inA + (long)sn1 * strA + (long)c * HWc + shw1                          \
                : inB + (long)sn1 * strB + (long)(c - cinA) * HWc + shw1;                \
            rb1 = *reinterpret_cast<const float4*>(p);                                   \
        }                                                                                \
    } while (0)

#define GEMM_STASH(BUF)                                                                  \
    do {                                                                                 \
        Ws[BUF][akk0 + 0][aoo0] = ra0.x; Ws[BUF][akk0 + 1][aoo0] = ra0.y;                \
        Ws[BUF][akk0 + 2][aoo0] = ra0.z; Ws[BUF][akk0 + 3][aoo0] = ra0.w;                \
        Ws[BUF][akk1 + 0][aoo1] = ra1.x; Ws[BUF][akk1 + 1][aoo1] = ra1.y;                \
        Ws[BUF][akk1 + 2][aoo1] = ra1.z; Ws[BUF][akk1 + 3][aoo1] = ra1.w;                \
        *reinterpret_cast<float4*>(&Bs[BUF][skk0][sp40]) = rb0;                          \
        *reinterpret_cast<float4*>(&Bs[BUF][skk1][sp41]) = rb1;                          \
    } while (0)

    GEMM_FETCH(0);
    GEMM_STASH(0);
    __syncthreads();

    for (int kc = 0; kc < nk; kc++) {
        const int cur = kc & 1;
        if (kc + 1 < nk) GEMM_FETCH((kc + 1) << 4);

#pragma unroll
        for (int kk = 0; kk < 16; kk++) {
            const float4 a0 = *reinterpret_cast<const float4*>(&Ws[cur][kk][ty << 2]);
            const float4 a1 = *reinterpret_cast<const float4*>(&Ws[cur][kk][64 + (ty << 2)]);
            const float4 b0 = *reinterpret_cast<const float4*>(&Bs[cur][kk][tx << 2]);
            const float4 b1 = *reinterpret_cast<const float4*>(&Bs[cur][kk][64 + (tx << 2)]);
            const unsigned long long bp0 = pk2(b0.x, b0.y), bp1 = pk2(b0.z, b0.w);
            const unsigned long long bp2 = pk2(b1.x, b1.y), bp3 = pk2(b1.z, b1.w);
            const float av[8] = {a0.x, a0.y, a0.z, a0.w, a1.x, a1.y, a1.z, a1.w};
#pragma unroll
            for (int i = 0; i < 8; i++) {
                const unsigned long long ap = pk2(av[i], av[i]);
                fma2(acc[i][0], ap, bp0);
                fma2(acc[i][1], ap, bp1);
                fma2(acc[i][2], ap, bp2);
                fma2(acc[i][3], ap, bp3);
            }
        }
        if (kc + 1 < nk) GEMM_STASH(cur ^ 1);
        __syncthreads();
    }

    // ------------------------- epilogue -------------------------
#pragma unroll
    for (int jg = 0; jg < 2; jg++) {
        const int col0 = jg * 64 + (tx << 2);
        const int q = q0 + col0;
        const int n = q / HWc;
        const int hw = q - n * HWc;
        int rel[4];
#pragma unroll
        for (int j = 0; j < 4; j++) {
            const int hwj = hw + j;
            const int h = hwj / 56;
            rel[j] = (hwj - h * 56) - h + 56;
        }
#pragma unroll
        for (int i = 0; i < 8; i++) {
            const int o = o0 + ((i < 4) ? ((ty << 2) + i) : (64 + (ty << 2) + i - 4));
            const float2 v01 = upk2(acc[i][jg * 2]);
            const float2 v23 = upk2(acc[i][jg * 2 + 1]);
            float v[4] = {v01.x, v01.y, v23.x, v23.y};
            if (EPI == 1) {
                const float s = e_g[o] * rsqrtf(e_v[o] + EPSf);
                const float t = e_b[o] - e_m[o] * s;
                const float bb = e_bias[o];
#pragma unroll
                for (int j = 0; j < 4; j++) {
                    float u = gelu_f((v[j] + bb) * s + t);
                    if (o < 128) u += __ldg(&e_pos[rel[j] * 128 + o]);
                    v[j] = u;
                }
            } else if (EPI == 2) {
                const float s = e_g[o] * rsqrtf(e_v[o] + EPSf);
                const float t = e_b[o] - e_m[o] * s;
#pragma unroll
                for (int j = 0; j < 4; j++) {
                    v[j] = gelu_f(v[j] * s + t) + __ldg(&e_pos[rel[j] * 128 + o]);
                }
            }
            float4 vv;
            vv.x = v[0]; vv.y = v[1]; vv.z = v[2]; vv.w = v[3];
            *reinterpret_cast<float4*>(&out[(long)n * strO + (long)o * HWc + hw]) = vv;
        }
    }
#undef GEMM_FETCH
#undef GEMM_STASH
}

// ---------------------------------------------------------------------------
// Strip conv. H-variant: xh[n,c,o,w] = b[c*56+o] + sum_{h',kw} W[(c*56+o)*168+h'*3+kw]*x1[n,c,h',w+kw-1]
// W-variant: xw[n,c,h,wo] = b[c*56+wo] + sum_{w',kh} W[(c*56+wo)*168+w'*3+kh]*x1[n,64+c,h+kh-1,w']
// Block = (c, n), 224 threads: tid>>2 selects o/wo in [0,56), tid&3 selects a
// 14-wide output strip. x1 plane staged in padded smem.
// ---------------------------------------------------------------------------
template<bool WVAR>
__global__ __launch_bounds__(224)
void strip_k(const float* __restrict__ Wg, const float* __restrict__ bias)
{
    __shared__ float xs[58][58];
    const int c = blockIdx.x;   // 0..63
    const int n = blockIdx.y;   // 0..15
    const int tid = threadIdx.x;

    for (int i = tid; i < 58 * 58; i += 224) ((float*)xs)[i] = 0.f;
    __syncthreads();
    const float* src = g_y + (long)n * Cc * HWc + (long)((WVAR ? 64 : 0) + c) * HWc;
    for (int i = tid; i < HWc; i += 224) {
        const int h = i / 56;
        xs[1 + h][1 + (i - h * 56)] = src[i];
    }
    __syncthreads();

    const int oo = tid >> 2;      // output row index (o or wo)
    const int grp = tid & 3;
    const int base0 = grp * 14;
    const float* wrow = Wg + ((long)c * 56 + oo) * 168;

    float acc[14];
    const float bval = __ldg(&bias[c * 56 + oo]);
#pragma unroll
    for (int i = 0; i < 14; i++) acc[i] = bval;

    if (!WVAR) {
        for (int hp = 0; hp < 56; hp++) {
            const float w0 = __ldg(&wrow[hp * 3 + 0]);
            const float w1 = __ldg(&wrow[hp * 3 + 1]);
            const float w2 = __ldg(&wrow[hp * 3 + 2]);
            float xv[16];
#pragma unroll
            for (int t = 0; t < 16; t++) xv[t] = xs[1 + hp][base0 + t];
#pragma unroll
            for (int i = 0; i < 14; i++) acc[i] += w0 * xv[i] + w1 * xv[i + 1] + w2 * xv[i + 2];
        }
        float* dst = g_cat + (long)n * C1c * HWc + (long)c * HWc + oo * 56 + base0;
#pragma unroll
        for (int i = 0; i < 14; i++) dst[i] = acc[i];
    } else {
        for (int wp = 0; wp < 56; wp++) {
            const float w0 = __ldg(&wrow[wp * 3 + 0]);
            const float w1 = __ldg(&wrow[wp * 3 + 1]);
            const float w2 = __ldg(&wrow[wp * 3 + 2]);
            float xv[16];
#pragma unroll
            for (int t = 0; t < 16; t++) xv[t] = xs[base0 + t][1 + wp];
#pragma unroll
            for (int i = 0; i < 14; i++) acc[i] += w0 * xv[i] + w1 * xv[i + 1] + w2 * xv[i + 2];
        }
        float* dst = g_cat + (long)n * C1c * HWc + (long)(64 + c) * HWc + oo;
#pragma unroll
        for (int i = 0; i < 14; i++) dst[(base0 + i) * 56] = acc[i];
    }
}

// ---------------------------------------------------------------------------
// Depthwise 3x7 (pad 1,3) + 7x3 (pad 3,1) on x2 = y[:,128:], plus channel mean
// of (x2h + x2w + x2). Block = (c, n), 256 threads.
// ---------------------------------------------------------------------------
__global__ __launch_bounds__(256)
void dw_k(const float* __restrict__ wh, const float* __restrict__ ww)
{
    __shared__ float xs[62][62];
    __shared__ float red[8];
    const int c = blockIdx.x, n = blockIdx.y;
    const int tid = threadIdx.x;

    for (int i = tid; i < 62 * 62; i += 256) ((float*)xs)[i] = 0.f;
    __syncthreads();
    const float* src = g_y + (long)n * Cc * HWc + (long)(128 + c) * HWc;
    for (int i = tid; i < HWc; i += 256) {
        const int h = i / 56;
        xs[3 + h][3 + (i - h * 56)] = src[i];
    }
    __syncthreads();

    float kh_[21], kw_[21];
#pragma unroll
    for (int i = 0; i < 21; i++) { kh_[i] = __ldg(&wh[c * 21 + i]); kw_[i] = __ldg(&ww[c * 21 + i]); }

    float lsum = 0.f;
    float* dh = g_x2h + (long)n * C1c * HWc + (long)c * HWc;
    float* dv = g_x2w + (long)n * C1c * HWc + (long)c * HWc;
    for (int i = tid; i < HWc; i += 256) {
        const int h = i / 56, w = i - h * 56;
        float vh = 0.f, vw = 0.f;
#pragma unroll
        for (int a = 0; a < 3; a++)
#pragma unroll
            for (int b = 0; b < 7; b++)
                vh += kh_[a * 7 + b] * xs[h + a + 2][w + b];
#pragma unroll
        for (int a = 0; a < 7; a++)
#pragma unroll
            for (int b = 0; b < 3; b++)
                vw += kw_[a * 3 + b] * xs[h + a][w + b + 2];
        const float x0 = xs[3 + h][3 + w];
        dh[i] = vh;
        dv[i] = vw;
        lsum += vh + vw + x0;
    }
#pragma unroll
    for (int off = 16; off; off >>= 1) lsum += __shfl_down_sync(0xffffffffu, lsum, off);
    if ((tid & 31) == 0) red[tid >> 5] = lsum;
    __syncthreads();
    if (tid == 0) {
        float s = 0.f;
#pragma unroll
        for (int i = 0; i < 8; i++) s += red[i];
        g_att[n * 128 + c] = s * (1.0f / HWc);
    }
}

// ---------------------------------------------------------------------------
// Tiny attention MLP: att[16,128] -> hidden 64 (gelu) -> 384 -> softmax over 3
// ---------------------------------------------------------------------------
__global__ __launch_bounds__(128)
void att_k(const float* __restrict__ w1, const float* __restrict__ b1,
           const float* __restrict__ w2, const float* __restrict__ b2)
{
    __shared__ float satt[128];
    __shared__ float shid[64];
    const int n = blockIdx.x, tid = threadIdx.x;
    satt[tid] = g_att[n * 128 + tid];
    __syncthreads();
    if (tid < 64) {
        float acc = b1[tid];
        for (int c = 0; c < 128; c++) acc += satt[c] * w1[tid * 128 + c];
        shid[tid] = gelu_f(acc);
    }
    __syncthreads();
    float v[3];
#pragma unroll
    for (int k = 0; k < 3; k++) {
        float acc = b2[tid * 3 + k];
        for (int h = 0; h < 64; h++) acc += shid[h] * w2[(tid * 3 + k) * 64 + h];
        v[k] = acc;
    }
    const float m = fmaxf(v[0], fmaxf(v[1], v[2]));
    const float e0 = expf(v[0] - m), e1 = expf(v[1] - m), e2 = expf(v[2] - m);
    const float s = e0 + e1 + e2;
    g_a[n * 384 + tid * 3 + 0] = e0 / s;
    g_a[n * 384 + tid * 3 + 1] = e1 / s;
    g_a[n * 384 + tid * 3 + 2] = e2 / s;
}

// ---------------------------------------------------------------------------
// x2n = x2h*a0 + x2w*a1 + x2*a2
// ---------------------------------------------------------------------------
__global__ __launch_bounds__(256)
void comb_k()
{
    const long total4 = (long)Nn * C1c * HWc / 4;
    for (long e4 = (long)blockIdx.x * 256 + threadIdx.x; e4 < total4; e4 += (long)gridDim.x * 256) {
        const long e = e4 * 4;
        const int n = (int)(e / ((long)C1c * HWc));
        const long r = e - (long)n * C1c * HWc;
        const int c = (int)(r / HWc);
        const int hw = (int)(r - (long)c * HWc);
        const float a0 = g_a[n * 384 + c * 3 + 0];
        const float a1 = g_a[n * 384 + c * 3 + 1];
        const float a2 = g_a[n * 384 + c * 3 + 2];
        const float4 h4 = *reinterpret_cast<const float4*>(&g_x2h[e]);
        const float4 w4 = *reinterpret_cast<const float4*>(&g_x2w[e]);
        const float4 x4 = *reinterpret_cast<const float4*>(&g_y[(long)n * Cc * HWc + (long)(128 + c) * HWc + hw]);
        float4 o4;
        o4.x = h4.x * a0 + w4.x * a1 + x4.x * a2;
        o4.y = h4.y * a0 + w4.y * a1 + x4.y * a2;
        o4.z = h4.z * a0 + w4.z * a1 + x4.z * a2;
        o4.w = h4.w * a0 + w4.w * a1 + x4.w * a2;
        *reinterpret_cast<float4*>(&g_x2n[e]) = o4;
    }
}

// ---------------------------------------------------------------------------
extern "C" void kernel_launch(void* const* d_in, const int* in_sizes, int n_in,
                              void* d_out, int out_size)
{
    const float* x      = (const float*)d_in[0];
    const float* mlp_w  = (const float*)d_in[1];
    const float* mlp_b  = (const float*)d_in[2];
    const float* bn1_g  = (const float*)d_in[3];
    const float* bn1_b  = (const float*)d_in[4];
    const float* bn1_m  = (const float*)d_in[5];
    const float* bn1_v  = (const float*)d_in[6];
    const float* pos_h  = (const float*)d_in[7];
    const float* pos_w  = (const float*)d_in[8];
    const float* pjh_w  = (const float*)d_in[9];
    const float* pjh_b  = (const float*)d_in[10];
    const float* pjw_w  = (const float*)d_in[11];
    const float* pjw_b  = (const float*)d_in[12];
    const float* fuse_h = (const float*)d_in[13];
    const float* bn2_g  = (const float*)d_in[14];
    const float* bn2_b  = (const float*)d_in[15];
    const float* bn2_m  = (const float*)d_in[16];
    const float* bn2_v  = (const float*)d_in[17];
    const float* fuse_w = (const float*)d_in[18];
    const float* fch_w  = (const float*)d_in[19];
    const float* fcw_w  = (const float*)d_in[20];
    const float* rw_w1  = (const float*)d_in[21];
    const float* rw_b1  = (const float*)d_in[22];
    const float* rw_w2  = (const float*)d_in[23];
    const float* rw_b2  = (const float*)d_in[24];
    const float* fout_w = (const float*)d_in[25];

    float *yp, *catp, *t1p, *u1p, *x2np;
    cudaGetSymbolAddress((void**)&yp,   g_y);
    cudaGetSymbolAddress((void**)&catp, g_cat);
    cudaGetSymbolAddress((void**)&t1p,  g_t1);
    cudaGetSymbolAddress((void**)&u1p,  g_u1);
    cudaGetSymbolAddress((void**)&x2np, g_x2n);

    const int sFull = Cc * HWc;   // 256-ch image stride
    const int sHalf = C1c * HWc;  // 128-ch image stride

    // GEMM1: y = gelu(bn(x@mlp_w + mlp_b)) ; ch<128 += pos_h
    gemm_k<1><<<dim3(Pc / 128, 2), 256>>>(mlp_w, 256, x, 256, sFull, x, sFull,
                                          yp, sFull, mlp_b, bn1_g, bn1_b, bn1_m, bn1_v, pos_h);

    // strip convs (read y ch 0..63 / 64..127, write g_cat ch 0..63 / 64..127)
    strip_k<false><<<dim3(64, 16), 224>>>(pjh_w, pjh_b);
    strip_k<true ><<<dim3(64, 16), 224>>>(pjw_w, pjw_b);

    // depthwise + channel means (reads y ch 128..255)
    dw_k<<<dim3(128, 16), 256>>>(fch_w, fcw_w);
    att_k<<<16, 128>>>(rw_w1, rw_b1, rw_w2, rw_b2);
    comb_k<<<1024, 256>>>();

    // GEMM2: t1 = gelu(bn(concat[cat, x1]@fuse_h)) + pos_w
    gemm_k<2><<<dim3(Pc / 128, 1), 256>>>(fuse_h, 256, catp, 128, sHalf, yp, sFull,
                                          t1p, sHalf, nullptr, bn2_g, bn2_b, bn2_m, bn2_v, pos_w);

    // GEMM3: u1 = concat[t1, x2]@fuse_w   (x2 = y ch 128..255 via pointer offset)
    gemm_k<0><<<dim3(Pc / 128, 1), 256>>>(fuse_w, 256, t1p, 128, sHalf, yp + 128 * HWc, sFull,
                                          u1p, sHalf, nullptr, nullptr, nullptr, nullptr, nullptr, nullptr);

    // GEMM4: out = concat[u1, x2n]@fuse_out
    gemm_k<0><<<dim3(Pc / 128, 2), 256>>>(fout_w, 256, u1p, 128, sHalf, x2np, sHalf,
                                          (float*)d_out, sFull, nullptr, nullptr, nullptr, nullptr, nullptr, nullptr);
}